// round 3
// baseline (speedup 1.0000x reference)
#include <cuda_runtime.h>

#define Bb 16
#define Ss 4096
#define Hh 1024
#define NN 2048
#define DWw 50
#define OD (Hh + DWw)   // 1074

#define NCH_W 8         // lastw chunks per batch
#define CH 32           // reduce2 chunks over output rows

__device__ float g_last_ctx[Bb * Hh];
__device__ float g_last_w[Bb * 64];
__device__ int   g_start[Bb][NN + 1];

__device__ __forceinline__ void atomicMaxF(float* addr, float val) {
    if (val >= 0.f) atomicMax((int*)addr, __float_as_int(val));
    else            atomicMin((unsigned int*)addr, __float_as_uint(val));
}

__device__ __forceinline__ float4 fmax4(float4 a, float4 b) {
    a.x = fmaxf(a.x, b.x); a.y = fmaxf(a.y, b.y);
    a.z = fmaxf(a.z, b.z); a.w = fmaxf(a.w, b.w);
    return a;
}

// Pass 1: word-span boundaries from sorted seg_ids (int4 vectorized) + scratch init.
__global__ void prep_kernel(const int* __restrict__ seg) {
    int b = blockIdx.x;
    int i = blockIdx.y * 256 + threadIdx.x;          // int4 index 0..1023
    const int4* s4 = (const int4*)(seg + (long)b * Ss);
    int4 v = s4[i];
    int s = i * 4;
    int prev = (s == 0) ? -1 : __ldg(seg + (long)b * Ss + s - 1);
    if (v.x != prev) g_start[b][v.x] = s;
    if (v.y != v.x)  g_start[b][v.y] = s + 1;
    if (v.z != v.y)  g_start[b][v.z] = s + 2;
    if (v.w != v.z)  g_start[b][v.w] = s + 3;
    if (s + 3 == Ss - 1) g_start[b][v.w + 1] = Ss;   // sentinel end

    if (blockIdx.y == 0) {
        float ninf = __int_as_float(0xFF800000);
        for (int k = threadIdx.x; k < Hh; k += 256) g_last_ctx[b * Hh + k] = ninf;
        if (threadIdx.x < 64) g_last_w[b * 64 + threadIdx.x] = ninf;
    }
}

// Pass 2: per-word segment max + concat; lastw reduction in extra blocks.
__global__ void fused_kernel(const float* __restrict__ ctx,
                             const float* __restrict__ wemb,
                             const int* __restrict__ ns_arr,
                             float* __restrict__ out) {
    int bx = blockIdx.x;
    int b  = blockIdx.y;
    int t  = threadIdx.x;            // 0..255
    int ns = ns_arr[b];

    if (bx < NN) {
        int n = bx;
        float* orow = out + ((long)b * NN + n) * OD;
        float2* o2 = (float2*)orow;   // rows are 8B-aligned (4296B stride)

        if (n >= ns) {                // padding: zero-fill (out is poisoned)
            for (int i = t; i < OD / 2; i += 256) o2[i] = make_float2(0.f, 0.f);
            return;
        }
        if (n == ns - 1) return;      // written by finish_kernel

        int start = __ldg(&g_start[b][n]);
        int end   = __ldg(&g_start[b][n + 1]);

        const float4* crow = (const float4*)(ctx + ((long)b * Ss + start) * Hh);
        float4 acc = crow[t];
        int cnt = end - start;
#pragma unroll 4
        for (int r = 1; r < cnt; r++) {
            acc = fmax4(acc, crow[(long)r * (Hh / 4) + t]);
        }
        o2[2 * t]     = make_float2(acc.x, acc.y);
        o2[2 * t + 1] = make_float2(acc.z, acc.w);
        if (t < DWw) orow[Hh + t] = wemb[((long)b * NN + n) * DWw + t];
        return;
    }

    // lastw: max over words 0..ns-1 of word_emb
    int rc = bx - NN;
    if (t >= DWw) return;
    int rows = ns;
    int per  = (rows + NCH_W - 1) / NCH_W;
    int r0 = rc * per;
    int r1 = min(rows, r0 + per);
    if (r0 >= r1) return;
    float acc = wemb[((long)b * NN + r0) * DWw + t];
#pragma unroll 4
    for (int r = r0 + 1; r < r1; r++) {
        acc = fmaxf(acc, wemb[((long)b * NN + r) * DWw + t]);
    }
    atomicMaxF(&g_last_w[b * 64 + t], acc);
}

// Pass 3: last_ctx from already-reduced output rows (words 0..wb-1, ~2.7x
// fewer bytes than raw ctx) + partial ctx rows of boundary word wb.
__global__ void reduce2_kernel(const float* __restrict__ ctx,
                               const int* __restrict__ seg,
                               const int* __restrict__ ns_arr,
                               const float* __restrict__ out) {
    int b = blockIdx.y;
    int c = blockIdx.x;
    int t = threadIdx.x;             // owns channels 4t..4t+3
    int ns = ns_arr[b];
    if (ns < 2) return;
    int wb = __ldg(seg + (long)b * Ss + ns - 2);  // word containing subword ns-2

    if (c < CH) {
        int per = (wb + CH - 1) / CH;
        int w0 = c * per;
        int w1 = min(wb, w0 + per);
        if (w0 >= w1) return;
        const float* base = out + ((long)b * NN + w0) * OD;
        float2 a0 = ((const float2*)base)[2 * t];
        float2 a1 = ((const float2*)base)[2 * t + 1];
        int cnt = w1 - w0;
#pragma unroll 4
        for (int w = 1; w < cnt; w++) {
            const float2* r = (const float2*)(base + (long)w * OD);
            float2 x0 = r[2 * t], x1 = r[2 * t + 1];
            a0.x = fmaxf(a0.x, x0.x); a0.y = fmaxf(a0.y, x0.y);
            a1.x = fmaxf(a1.x, x1.x); a1.y = fmaxf(a1.y, x1.y);
        }
        float* dst = g_last_ctx + b * Hh + 4 * t;
        atomicMaxF(dst + 0, a0.x);
        atomicMaxF(dst + 1, a0.y);
        atomicMaxF(dst + 2, a1.x);
        atomicMaxF(dst + 3, a1.y);
    } else {
        // partial: ctx rows start[wb] .. ns-2
        int r0 = __ldg(&g_start[b][wb]);
        int r1 = ns - 1;
        if (r0 >= r1) return;
        const float4* base = (const float4*)(ctx + ((long)b * Ss + r0) * Hh);
        float4 acc = base[t];
        int cnt = r1 - r0;
        for (int r = 1; r < cnt; r++) acc = fmax4(acc, base[(long)r * (Hh / 4) + t]);
        float* dst = g_last_ctx + b * Hh + 4 * t;
        atomicMaxF(dst + 0, acc.x);
        atomicMaxF(dst + 1, acc.y);
        atomicMaxF(dst + 2, acc.z);
        atomicMaxF(dst + 3, acc.w);
    }
}

// Pass 4: write the special last-word row.
__global__ void finish_kernel(const int* __restrict__ ns_arr,
                              float* __restrict__ out) {
    int b = blockIdx.x;
    int t = threadIdx.x;
    int n = ns_arr[b] - 1;
    float* orow = out + ((long)b * NN + n) * OD;
    float2* o2 = (float2*)orow;
    float4 v = ((const float4*)(g_last_ctx + b * Hh))[t];
    o2[2 * t]     = make_float2(v.x, v.y);
    o2[2 * t + 1] = make_float2(v.z, v.w);
    if (t < DWw) orow[Hh + t] = g_last_w[b * 64 + t];
}

extern "C" void kernel_launch(void* const* d_in, const int* in_sizes, int n_in,
                              void* d_out, int out_size) {
    const float* ctx  = (const float*)d_in[0];   // [B, S, H]
    const float* wemb = (const float*)d_in[1];   // [B, N, DW]
    const int*   seg  = (const int*)d_in[2];     // [B, S]
    const int*   ns   = (const int*)d_in[3];     // [B]
    float* out = (float*)d_out;                  // [B, N, H+DW]

    prep_kernel<<<dim3(Bb, 4), 256>>>(seg);
    fused_kernel<<<dim3(NN + NCH_W, Bb), 256>>>(ctx, wemb, ns, out);
    reduce2_kernel<<<dim3(CH + 1, Bb), 256>>>(ctx, seg, ns, out);
    finish_kernel<<<Bb, 256>>>(ns, out);
}